// round 12
// baseline (speedup 1.0000x reference)
#include <cuda_runtime.h>
#include <cuda_bf16.h>

// Invert f(x) = a*x + (1-a)*softplus(x), a = 0.1 + 0.4*sigmoid(raw_alpha[0]).
//
// Unshifted-exponent form (valid for x in [-121, +88); this input gives
// x in [-121, +17]): with e = exp(x), c = 1-a:
//   softplus(x) = ln(1+e)            (e underflows to 0 for x<<0 -> exact)
//   f'(x)*(1+e) = a + e              (NO select, NO abs)
//   f''(x)*(1+e)^2 = c*e
// Halley: r = 1/(a+e); w = F*r; x1 = x - w*(1+e) - (ch*e)*(w*w*r... see code)
//
// Branchless seed:
//   x0b = min(y, y/a)                (FMNMX)
//   den = 1 + x0b*(al + ga*x0b) + |x0b|*(be + de*x0b)   (|.| is a free SASS
//         operand modifier) -- identical to the per-sign (p,q) rational fit
//         of R7: p,q = (1.486,1.31) y>0 / (-0.341,0.279) y<=0.
//   x0  = x0b - 1.41/den
// Seed error <= ~0.1 => one cubic step lands ~1e-7..1e-5, >> 1e-3 gate.

#define ELEMS_PER_THREAD 8

__device__ __forceinline__ float solve_one(float y, float a, float c,
                                           float cln2, float ch, float inv_a) {
    // ---- branchless rational-corrected seed ----
    float x0b = fminf(y, y * inv_a);
    float ax0 = fabsf(x0b);                               // free operand modifier
    float den0 = fmaf(x0b, fmaf(0.7945f, x0b, 0.5725f),
                      fmaf(ax0, fmaf(0.5155f, x0b, 0.9135f), 1.0f));
    float x = fmaf(-1.41f, __fdividef(1.0f, den0), x0b);  // MUFU.RCP

    // ---- one Halley (cubic) step, e = exp(x) form ----
    float e   = __expf(x);                                // FMUL + MUFU.EX2
    float ope = 1.0f + e;
    float L2  = __log2f(ope);                             // MUFU.LG2
    float F   = fmaf(cln2, L2, fmaf(a, x, -y));           // f(x) - y
    float dnm = a + e;                                    // f'(x)*(1+e)
    float r   = __fdividef(1.0f, dnm);                    // MUFU.RCP
    float w   = F * r;
    float g   = w * ope;                                  // Newton step F/f'
    float h   = (ch * e) * (w * r);                       // F*f''/(2 f'^2)
    return fmaf(-g, h, x - g);                            // x - g*(1+h)
}

__global__ void __launch_bounds__(256)
inv_leaky_softplus_kernel(const float* __restrict__ y,
                          const float* __restrict__ raw_alpha,
                          float* __restrict__ out,
                          int n)
{
    // per-thread scalar setup (amortized over 8 elements)
    float ra    = raw_alpha[0];
    float a     = fmaf(0.4f, __fdividef(1.0f, 1.0f + __expf(-ra)), 0.1f);
    float c     = 1.0f - a;
    float cln2  = c * 0.6931471805599453f;
    float ch    = 0.5f * c;
    float inv_a = __fdividef(1.0f, a);

    int base = (blockIdx.x * blockDim.x + threadIdx.x) * ELEMS_PER_THREAD;
    if (base + ELEMS_PER_THREAD - 1 < n) {
        float4 v0 = *reinterpret_cast<const float4*>(y + base);
        float4 v1 = *reinterpret_cast<const float4*>(y + base + 4);
        float4 r0, r1;
        r0.x = solve_one(v0.x, a, c, cln2, ch, inv_a);
        r0.y = solve_one(v0.y, a, c, cln2, ch, inv_a);
        r0.z = solve_one(v0.z, a, c, cln2, ch, inv_a);
        r0.w = solve_one(v0.w, a, c, cln2, ch, inv_a);
        r1.x = solve_one(v1.x, a, c, cln2, ch, inv_a);
        r1.y = solve_one(v1.y, a, c, cln2, ch, inv_a);
        r1.z = solve_one(v1.z, a, c, cln2, ch, inv_a);
        r1.w = solve_one(v1.w, a, c, cln2, ch, inv_a);
        *reinterpret_cast<float4*>(out + base)     = r0;
        *reinterpret_cast<float4*>(out + base + 4) = r1;
    } else {
        for (int i = base; i < n; ++i) {
            out[i] = solve_one(y[i], a, c, cln2, ch, inv_a);
        }
    }
}

extern "C" void kernel_launch(void* const* d_in, const int* in_sizes, int n_in,
                              void* d_out, int out_size)
{
    const float* y  = (const float*)d_in[0];
    const float* ra = (const float*)d_in[1];
    float* out      = (float*)d_out;
    int n = in_sizes[0];

    int threads = 256;
    int elems_per_block = threads * ELEMS_PER_THREAD;
    int blocks = (n + elems_per_block - 1) / elems_per_block;
    inv_leaky_softplus_kernel<<<blocks, threads>>>(y, ra, out, n);
}